// round 6
// baseline (speedup 1.0000x reference)
#include <cuda_runtime.h>
#include <cuda_fp16.h>
#include <cstdint>
#include <cstddef>

// AspectAttention round 6: fp16 mma.sync m16n8k16, 512 threads / 16 warps (occupancy push).
// CTA: 128 rows x 256 cols, warp grid 4m x 4n, warp tile 32x64, acc=64 regs/thread.
// W fragment-packed fp16 as uint4 (2 k-steps per LDS.128), fully smem-resident.
// A: LDG f32 -> cvt -> STS fp16 (XOR swizzle), fragments via ldmatrix.x4, KC=64, 2 slots.

#define THREADS   512
#define KC        64
#define BOFF      0
#define BBYTES    131072                      // 8 ssp x 256 col x 4 tig x 16B
#define AOFF(s)   (BBYTES + (s) * 16384)      // 128 rows x 128B fp16
#define RP_OFF    (BBYTES + 32768)            // rowpart: 512 floats
#define CP_OFF    (RP_OFF + 2048)             // colpart: 16 warps x 64 cols
#define SMEM_BYTES (CP_OFF + 4096)

__device__ __half g_Wpack[8 * 256 * 4 * 8];   // [ssp][col][tig][8 halves = uint4]

// ---------------- helpers ----------------
__device__ __forceinline__ float tanh_fast(float x) {
    float y; asm("tanh.approx.f32 %0, %1;" : "=f"(y) : "f"(x)); return y;
}
__device__ __forceinline__ uint32_t pack2(float hi, float lo) {
    uint32_t r; asm("cvt.rn.f16x2.f32 %0, %1, %2;" : "=r"(r) : "f"(hi), "f"(lo)); return r;
}
__device__ __forceinline__ void mma_fp16(float (&c)[4],
                                         uint32_t a0, uint32_t a1, uint32_t a2, uint32_t a3,
                                         uint32_t b0, uint32_t b1) {
    asm volatile(
        "mma.sync.aligned.m16n8k16.row.col.f32.f16.f16.f32 "
        "{%0,%1,%2,%3},{%4,%5,%6,%7},{%8,%9},{%0,%1,%2,%3};"
        : "+f"(c[0]), "+f"(c[1]), "+f"(c[2]), "+f"(c[3])
        : "r"(a0), "r"(a1), "r"(a2), "r"(a3), "r"(b0), "r"(b1));
}
__device__ __forceinline__ void ldmatrix4(uint32_t (&d)[4], uint32_t addr) {
    asm volatile("ldmatrix.sync.aligned.m8n8.x4.shared.b16 {%0,%1,%2,%3}, [%4];"
                 : "=r"(d[0]), "=r"(d[1]), "=r"(d[2]), "=r"(d[3]) : "r"(addr));
}
__device__ __forceinline__ void cp_async16(uint32_t sa, const void* g) {
    asm volatile("cp.async.cg.shared.global [%0], [%1], 16;" :: "r"(sa), "l"(g));
}

// ---------------- W pack: uint4 = B frags for k-step pair (2*ssp, 2*ssp+1) ------
__global__ void pack_w_kernel(const float* __restrict__ W) {
    const int ssp = blockIdx.x;      // 0..7
    const int col = threadIdx.x;     // 0..255
    #pragma unroll
    for (int t = 0; t < 4; ++t) {
        __half* dst = g_Wpack + (((ssp * 256 + col) * 4 + t) * 8);
        const int k0 = 32 * ssp + 2 * t;       // sg even = 2*ssp
        dst[0] = __float2half_rn(W[(k0)      * 256 + col]);
        dst[1] = __float2half_rn(W[(k0 + 1)  * 256 + col]);
        dst[2] = __float2half_rn(W[(k0 + 8)  * 256 + col]);
        dst[3] = __float2half_rn(W[(k0 + 9)  * 256 + col]);
        const int k1 = k0 + 16;                // sg odd
        dst[4] = __float2half_rn(W[(k1)      * 256 + col]);
        dst[5] = __float2half_rn(W[(k1 + 1)  * 256 + col]);
        dst[6] = __float2half_rn(W[(k1 + 8)  * 256 + col]);
        dst[7] = __float2half_rn(W[(k1 + 9)  * 256 + col]);
    }
}

// ---------------- main kernel ----------------
__global__ __launch_bounds__(THREADS, 1)
void aspect_attention_kernel(const float* __restrict__ h,
                             const float* __restrict__ bias,
                             float* __restrict__ out) {
    extern __shared__ __align__(16) char dynsmem[];
    const uint32_t smem_u32 = (uint32_t)__cvta_generic_to_shared(dynsmem);

    const int tid  = threadIdx.x;
    const int w    = tid >> 5;
    const int lane = tid & 31;
    const int g    = lane >> 2;
    const int tig  = lane & 3;
    const int wm   = w & 3;        // row block: wm*32
    const int wn   = w >> 2;       // col block: wn*64

    // ldmatrix per-thread constants
    const int arow0  = wm * 32 + (lane & 7) + ((lane >> 3) & 1) * 8;   // + mf*16
    const uint32_t X = ((uint32_t)(lane & 7)) << 4;
    const uint32_t kL = ((uint32_t)((lane >> 4) & 1)) * 16;            // + ss_local*32

    // LDG/STS constants
    const int srow  = tid >> 4;      // 0..31, + j*32
    const int squad = tid & 15;

    const float* hb = h + (size_t)blockIdx.x * (128 * 256);
    const uint4* sBq = (const uint4*)(dynsmem + BOFF);

    float acc[2][8][4];
    #pragma unroll
    for (int mf = 0; mf < 2; ++mf)
        #pragma unroll
        for (int nt = 0; nt < 8; ++nt)
            #pragma unroll
            for (int i = 0; i < 4; ++i) acc[mf][nt][i] = 0.0f;

    float4 buf[4];

    #define LDG_CHUNK(c) do {                                                     \
        const float* src_ = hb + (c) * KC;                                        \
        _Pragma("unroll")                                                         \
        for (int j = 0; j < 4; ++j)                                               \
            buf[j] = *(const float4*)(src_ + (srow + j * 32) * 256 + squad * 4);  \
    } while (0)

    #define STS_CHUNK(slot) do {                                                  \
        uint32_t base_ = smem_u32 + AOFF(slot);                                   \
        _Pragma("unroll")                                                         \
        for (int j = 0; j < 4; ++j) {                                             \
            uint32_t b_ = (uint32_t)((srow + j * 32) * 128 + squad * 8);          \
            uint32_t sw_ = b_ ^ ((b_ >> 3) & 0x70);                               \
            uint32_t u0_ = pack2(buf[j].y, buf[j].x);                             \
            uint32_t u1_ = pack2(buf[j].w, buf[j].z);                             \
            asm volatile("st.shared.v2.u32 [%0], {%1,%2};"                        \
                         :: "r"(base_ + sw_), "r"(u0_), "r"(u1_));                \
        }                                                                         \
    } while (0)

    #define COMPUTE(c) do {                                                       \
        uint32_t abase_ = smem_u32 + AOFF((c) & 1);                               \
        _Pragma("unroll")                                                         \
        for (int sp = 0; sp < 2; ++sp) {                                          \
            const int ssp_ = (c) * 2 + sp;                                        \
            uint32_t a[2][2][4];                                                  \
            _Pragma("unroll")                                                     \
            for (int mf = 0; mf < 2; ++mf)                                        \
                _Pragma("unroll")                                                 \
                for (int e = 0; e < 2; ++e) {                                     \
                    uint32_t b_ = (uint32_t)((arow0 + mf * 16) * 128)             \
                                + (uint32_t)(sp * 2 + e) * 32 + kL;               \
                    ldmatrix4(a[mf][e], abase_ + (b_ ^ X));                       \
                }                                                                 \
            _Pragma("unroll")                                                     \
            for (int nt = 0; nt < 8; ++nt) {                                      \
                int col_ = wn * 64 + nt * 8 + g;                                  \
                uint4 bb_ = sBq[(ssp_ * 256 + col_) * 4 + tig];                   \
                mma_fp16(acc[0][nt], a[0][0][0], a[0][0][1], a[0][0][2], a[0][0][3], bb_.x, bb_.y); \
                mma_fp16(acc[1][nt], a[1][0][0], a[1][0][1], a[1][0][2], a[1][0][3], bb_.x, bb_.y); \
                mma_fp16(acc[0][nt], a[0][1][0], a[0][1][1], a[0][1][2], a[0][1][3], bb_.z, bb_.w); \
                mma_fp16(acc[1][nt], a[1][1][0], a[1][1][1], a[1][1][2], a[1][1][3], bb_.z, bb_.w); \
            }                                                                     \
        }                                                                         \
    } while (0)

    // ---- prologue: B resident via cp.async; chunk0 LDG->STS; chunk1 LDG ----
    {
        const char* bsrc = (const char*)g_Wpack;
        #pragma unroll
        for (int it = 0; it < 16; ++it) {
            int i_ = it * THREADS + tid;
            cp_async16(smem_u32 + BOFF + i_ * 16, bsrc + i_ * 16);
        }
        asm volatile("cp.async.commit_group;");
    }
    LDG_CHUNK(0);
    STS_CHUNK(0);
    LDG_CHUNK(1);
    asm volatile("cp.async.wait_group 0;");
    __syncthreads();

    // ---- main loop (4 chunks of KC=64) ----
    COMPUTE(0);
    __syncthreads();
    STS_CHUNK(1);          // buf = chunk 1
    LDG_CHUNK(2);
    __syncthreads();

    COMPUTE(1);
    __syncthreads();
    STS_CHUNK(0);          // buf = chunk 2
    LDG_CHUNK(3);
    __syncthreads();

    COMPUTE(2);
    __syncthreads();
    STS_CHUNK(1);          // buf = chunk 3
    __syncthreads();

    COMPUTE(3);

    // ---- epilogue phase 1: e = exp(tanh(s + bias)); column partial sums (32 rows) ----
    float psum[16];
    #pragma unroll
    for (int j = 0; j < 16; ++j) psum[j] = 0.0f;

    #pragma unroll
    for (int mf = 0; mf < 2; ++mf)
        #pragma unroll
        for (int hi = 0; hi < 2; ++hi) {
            int row = wm * 32 + mf * 16 + hi * 8 + g;
            const float* brow = bias + (row & 63) * 256 + wn * 64 + 2 * tig;
            #pragma unroll
            for (int nt = 0; nt < 8; ++nt) {
                float2 bb = *(const float2*)(brow + nt * 8);
                float e0 = __expf(tanh_fast(acc[mf][nt][2 * hi + 0] + bb.x));
                float e1 = __expf(tanh_fast(acc[mf][nt][2 * hi + 1] + bb.y));
                acc[mf][nt][2 * hi + 0] = e0;
                acc[mf][nt][2 * hi + 1] = e1;
                psum[nt * 2 + 0] += e0;
                psum[nt * 2 + 1] += e1;
            }
        }

    // butterfly over g bits: every lane holds 32-row partial colsum
    #pragma unroll
    for (int j = 0; j < 16; ++j) {
        psum[j] += __shfl_xor_sync(0xffffffffu, psum[j], 4);
        psum[j] += __shfl_xor_sync(0xffffffffu, psum[j], 8);
        psum[j] += __shfl_xor_sync(0xffffffffu, psum[j], 16);
    }

    // exchange with wm-partner warp (w^1) to complete the 64-row batch colsum
    float* colpart = (float*)(dynsmem + CP_OFF);
    __syncthreads();                 // A slots dead; colpart region is fresh
    if (g == 0) {
        #pragma unroll
        for (int nt = 0; nt < 8; ++nt) {
            colpart[w * 64 + nt * 8 + 2 * tig + 0] = psum[nt * 2 + 0];
            colpart[w * 64 + nt * 8 + 2 * tig + 1] = psum[nt * 2 + 1];
        }
    }
    __syncthreads();
    {
        const float* pc = colpart + (w ^ 1) * 64;
        #pragma unroll
        for (int nt = 0; nt < 8; ++nt) {
            psum[nt * 2 + 0] = 1.0f / (psum[nt * 2 + 0] + pc[nt * 8 + 2 * tig + 0]);
            psum[nt * 2 + 1] = 1.0f / (psum[nt * 2 + 1] + pc[nt * 8 + 2 * tig + 1]);
        }
    }

    // ---- phase 2: out[row] = sum_col e * inv * h ----
    float part[4];
    #pragma unroll
    for (int mf = 0; mf < 2; ++mf)
        #pragma unroll
        for (int hi = 0; hi < 2; ++hi) {
            int row = wm * 32 + mf * 16 + hi * 8 + g;
            const float* hrow = hb + row * 256 + wn * 64 + 2 * tig;
            float p = 0.0f;
            #pragma unroll
            for (int nt = 0; nt < 8; ++nt) {
                float2 hh = *(const float2*)(hrow + nt * 8);
                p += acc[mf][nt][2 * hi + 0] * psum[nt * 2 + 0] * hh.x;
                p += acc[mf][nt][2 * hi + 1] * psum[nt * 2 + 1] * hh.y;
            }
            part[mf * 2 + hi] = p;
        }

    #pragma unroll
    for (int s = 0; s < 4; ++s) {
        part[s] += __shfl_xor_sync(0xffffffffu, part[s], 1);
        part[s] += __shfl_xor_sync(0xffffffffu, part[s], 2);
    }
    float* rowpart = (float*)(dynsmem + RP_OFF);
    if (tig == 0) {
        #pragma unroll
        for (int s = 0; s < 4; ++s) {
            int row = wm * 32 + (s >> 1) * 16 + (s & 1) * 8 + g;
            rowpart[wn * 128 + row] = part[s];
        }
    }
    __syncthreads();

    if (tid < 128) {
        float v = rowpart[tid] + rowpart[128 + tid] + rowpart[256 + tid] + rowpart[384 + tid];
        out[(size_t)blockIdx.x * 128 + tid] = v;
    }
}

extern "C" void kernel_launch(void* const* d_in, const int* in_sizes, int n_in,
                              void* d_out, int out_size) {
    const float* h    = (const float*)d_in[0];  // [4096, 64, 256]
    const float* W    = (const float*)d_in[1];  // [256, 256]
    const float* bias = (const float*)d_in[2];  // [64, 256]
    float* out = (float*)d_out;                 // [4096, 64]

    pack_w_kernel<<<8, 256>>>(W);

    cudaFuncSetAttribute(aspect_attention_kernel,
                         cudaFuncAttributeMaxDynamicSharedMemorySize, SMEM_BYTES);
    aspect_attention_kernel<<<2048, THREADS, SMEM_BYTES>>>(h, bias, out);
}

// round 7
// speedup vs baseline: 1.2079x; 1.2079x over previous
#include <cuda_runtime.h>
#include <cuda_fp16.h>
#include <cstdint>
#include <cstddef>

// AspectAttention round 7: fp16 mma.sync m16n8k16 with MANUAL SOFTWARE PIPELINING.
// 256 thr = 8 warps (2m x 4n), warp tile 64x64 (best traffic config, R4/R5).
// W fragment-packed fp16, smem-resident (128KB). A staged fp16 in 4 FIXED slots
// (64KB) with XOR swizzle; ldmatrix.x4 A double-buffered one k-step ahead; B
// fragments rotate through a 2-deep register buffer, one LDS between MMA groups.
// Phase-2 reads h from the resident fp16 A slots (no global re-read).

#define THREADS   256
#define BOFF      0
#define BBYTES    131072                      // 16 sg x 256 col x 4 tig x 8B
#define AOFF(c)   (BBYTES + (c) * 16384)      // 4 fixed slots: 128 rows x 128B fp16
#define RP_OFF    (BBYTES + 65536)            // rowpart: 512 floats
#define SMEM_BYTES (RP_OFF + 2048)            // ~194 KB

__device__ __half g_Wpack[16 * 256 * 16];     // [sg][col][tig][{b0.lo,b0.hi,b1.lo,b1.hi}]

// ---------------- helpers ----------------
__device__ __forceinline__ float tanh_fast(float x) {
    float y; asm("tanh.approx.f32 %0, %1;" : "=f"(y) : "f"(x)); return y;
}
__device__ __forceinline__ uint32_t pack2(float hi, float lo) {
    uint32_t r; asm("cvt.rn.f16x2.f32 %0, %1, %2;" : "=r"(r) : "f"(hi), "f"(lo)); return r;
}
__device__ __forceinline__ void mma_fp16(float (&c)[4],
                                         uint32_t a0, uint32_t a1, uint32_t a2, uint32_t a3,
                                         uint32_t b0, uint32_t b1) {
    asm volatile(
        "mma.sync.aligned.m16n8k16.row.col.f32.f16.f16.f32 "
        "{%0,%1,%2,%3},{%4,%5,%6,%7},{%8,%9},{%0,%1,%2,%3};"
        : "+f"(c[0]), "+f"(c[1]), "+f"(c[2]), "+f"(c[3])
        : "r"(a0), "r"(a1), "r"(a2), "r"(a3), "r"(b0), "r"(b1));
}
__device__ __forceinline__ void ldmatrix4(uint32_t (&d)[4], uint32_t addr) {
    asm volatile("ldmatrix.sync.aligned.m8n8.x4.shared.b16 {%0,%1,%2,%3}, [%4];"
                 : "=r"(d[0]), "=r"(d[1]), "=r"(d[2]), "=r"(d[3]) : "r"(addr));
}
__device__ __forceinline__ void cp_async16(uint32_t sa, const void* g) {
    asm volatile("cp.async.cg.shared.global [%0], [%1], 16;" :: "r"(sa), "l"(g));
}

// ---------------- W pack: fp16 fragment order (R4, proven) ----------------
__global__ void pack_w_kernel(const float* __restrict__ W) {
    const int s   = blockIdx.x;      // 0..15 (sg)
    const int col = threadIdx.x;     // 0..255
    #pragma unroll
    for (int t = 0; t < 4; ++t) {
        __half* dst = g_Wpack + ((s * 256 + col) * 4 + t) * 4;
        dst[0] = __float2half_rn(W[(16 * s + 2 * t)     * 256 + col]);
        dst[1] = __float2half_rn(W[(16 * s + 2 * t + 1) * 256 + col]);
        dst[2] = __float2half_rn(W[(16 * s + 2 * t + 8) * 256 + col]);
        dst[3] = __float2half_rn(W[(16 * s + 2 * t + 9) * 256 + col]);
    }
}

// ---------------- main kernel ----------------
__global__ __launch_bounds__(THREADS, 1)
void aspect_attention_kernel(const float* __restrict__ h,
                             const float* __restrict__ bias,
                             float* __restrict__ out) {
    extern __shared__ __align__(16) char dynsmem[];
    const uint32_t smem_u32 = (uint32_t)__cvta_generic_to_shared(dynsmem);

    const int tid  = threadIdx.x;
    const int w    = tid >> 5;
    const int lane = tid & 31;
    const int g    = lane >> 2;
    const int tig  = lane & 3;
    const int wm   = w & 1;        // row block: wm*64
    const int wn   = w >> 1;       // col block: wn*64

    // ldmatrix per-thread constants (R5, proven)
    const int arow0  = wm * 64 + (lane & 7) + ((lane >> 3) & 1) * 8;  // + mf*16
    const uint32_t X  = ((uint32_t)(lane & 7)) << 4;
    const uint32_t kL = ((uint32_t)((lane >> 4) & 1)) * 16;

    // LDG/STS constants (R5, proven)
    const int srow  = tid >> 4;      // + j*16
    const int squad = tid & 15;

    const float* hb = h + (size_t)blockIdx.x * (128 * 256);

    float acc[4][8][4];
    #pragma unroll
    for (int mf = 0; mf < 4; ++mf)
        #pragma unroll
        for (int nt = 0; nt < 8; ++nt)
            #pragma unroll
            for (int i = 0; i < 4; ++i) acc[mf][nt][i] = 0.0f;

    float4 buf[8];

    #define LDG_CHUNK(c) do {                                                     \
        const float* src_ = hb + (c) * 64;                                        \
        _Pragma("unroll")                                                         \
        for (int j = 0; j < 8; ++j)                                               \
            buf[j] = *(const float4*)(src_ + (srow + j * 16) * 256 + squad * 4);  \
    } while (0)

    #define STS_CHUNK(c) do {                                                     \
        uint32_t base_ = smem_u32 + AOFF(c);                                      \
        _Pragma("unroll")                                                         \
        for (int j = 0; j < 8; ++j) {                                             \
            uint32_t b_ = (uint32_t)((srow + j * 16) * 128 + squad * 8);          \
            uint32_t sw_ = b_ ^ ((b_ >> 3) & 0x70);                               \
            uint32_t u0_ = pack2(buf[j].y, buf[j].x);                             \
            uint32_t u1_ = pack2(buf[j].w, buf[j].z);                             \
            asm volatile("st.shared.v2.u32 [%0], {%1,%2};"                        \
                         :: "r"(base_ + sw_), "r"(u0_), "r"(u1_));                \
        }                                                                         \
    } while (0)

    // pipeline registers
    uint32_t A0[4][4], A1[4][4];
    uint32_t Bb[2][2];

    #define LOAD_A(slot, ss, A_) do {                                             \
        uint32_t ab_ = smem_u32 + AOFF(slot);                                     \
        _Pragma("unroll")                                                         \
        for (int mf = 0; mf < 4; ++mf) {                                          \
            uint32_t b_ = (uint32_t)((arow0 + mf * 16) * 128) + kL + (ss) * 32;   \
            ldmatrix4(A_[mf], ab_ + (b_ ^ X));                                    \
        }                                                                         \
    } while (0)

    #define LDB(sg, nt, p) do {                                                   \
        uint32_t ba_ = smem_u32 + BOFF +                                          \
            (uint32_t)(((((sg) * 256 + wn * 64 + (nt) * 8 + g) * 4) + tig) * 8);  \
        asm volatile("ld.shared.v2.u32 {%0,%1}, [%2];"                            \
                     : "=r"(Bb[p][0]), "=r"(Bb[p][1]) : "r"(ba_));                \
    } while (0)

    // One k16 step: prefetch B one nt ahead; at nt==7 prefetch first B of next sg.
    #define NTLOOP(sg, A_, last) do {                                             \
        _Pragma("unroll")                                                         \
        for (int nt = 0; nt < 8; ++nt) {                                          \
            if (nt < 7)        LDB((sg), nt + 1, (nt + 1) & 1);                   \
            else if (!(last))  LDB((sg) + 1, 0, 0);                               \
            _Pragma("unroll")                                                     \
            for (int mf = 0; mf < 4; ++mf)                                        \
                mma_fp16(acc[mf][nt],                                             \
                         A_[mf][0], A_[mf][1], A_[mf][2], A_[mf][3],              \
                         Bb[nt & 1][0], Bb[nt & 1][1]);                           \
        }                                                                         \
    } while (0)

    // Chunk body: entering with A0 = A(sg=4c), Bb[0] = B(4c, 0).
    #define CHUNK_BODY(c) do {                                                    \
        LOAD_A((c), 1, A1);  NTLOOP(4 * (c) + 0, A0, 0);                          \
        LOAD_A((c), 2, A0);  NTLOOP(4 * (c) + 1, A1, 0);                          \
        LOAD_A((c), 3, A1);  NTLOOP(4 * (c) + 2, A0, 0);                          \
                             NTLOOP(4 * (c) + 3, A1, ((c) == 3));                 \
    } while (0)

    // ---- prologue: B resident via cp.async; chunk0 LDG->STS; chunk1 LDG ----
    {
        const char* bsrc = (const char*)g_Wpack;
        #pragma unroll
        for (int it = 0; it < 32; ++it) {
            int i_ = it * THREADS + tid;
            cp_async16(smem_u32 + BOFF + i_ * 16, bsrc + i_ * 16);
        }
        asm volatile("cp.async.commit_group;");
    }
    LDG_CHUNK(0);
    STS_CHUNK(0);
    LDG_CHUNK(1);
    asm volatile("cp.async.wait_group 0;");
    __syncthreads();

    // ---- pipelined main loop (4 chunks, fixed slots, 1 barrier each) ----
    LOAD_A(0, 0, A0);
    LDB(0, 0, 0);
    CHUNK_BODY(0);

    STS_CHUNK(1); LDG_CHUNK(2);
    __syncthreads();
    LOAD_A(1, 0, A0);          // Bb[0] already holds B(4,0)
    CHUNK_BODY(1);

    STS_CHUNK(2); LDG_CHUNK(3);
    __syncthreads();
    LOAD_A(2, 0, A0);
    CHUNK_BODY(2);

    STS_CHUNK(3);
    __syncthreads();
    LOAD_A(3, 0, A0);
    CHUNK_BODY(3);

    // ---- epilogue phase 1: e = exp(tanh(s + bias)); intra-warp column sums ----
    float psum[16];
    #pragma unroll
    for (int j = 0; j < 16; ++j) psum[j] = 0.0f;

    #pragma unroll
    for (int mf = 0; mf < 4; ++mf)
        #pragma unroll
        for (int hi = 0; hi < 2; ++hi) {
            int row = wm * 64 + mf * 16 + hi * 8 + g;
            const float* brow = bias + (row & 63) * 256 + wn * 64 + 2 * tig;
            #pragma unroll
            for (int nt = 0; nt < 8; ++nt) {
                float2 bb = *(const float2*)(brow + nt * 8);
                float e0 = __expf(tanh_fast(acc[mf][nt][2 * hi + 0] + bb.x));
                float e1 = __expf(tanh_fast(acc[mf][nt][2 * hi + 1] + bb.y));
                acc[mf][nt][2 * hi + 0] = e0;
                acc[mf][nt][2 * hi + 1] = e1;
                psum[nt * 2 + 0] += e0;
                psum[nt * 2 + 1] += e1;
            }
        }

    #pragma unroll
    for (int j = 0; j < 16; ++j) {
        psum[j] += __shfl_xor_sync(0xffffffffu, psum[j], 4);
        psum[j] += __shfl_xor_sync(0xffffffffu, psum[j], 8);
        psum[j] += __shfl_xor_sync(0xffffffffu, psum[j], 16);
        psum[j] = 1.0f / psum[j];            // inv(colsum)
    }

    // ---- phase 2: out[row] = sum_col e * inv * h (h from resident fp16 slots) ----
    const uint32_t aslot = smem_u32 + AOFF(wn);     // warp's 64-col strip lives in slot wn
    float part[8];
    #pragma unroll
    for (int mf = 0; mf < 4; ++mf)
        #pragma unroll
        for (int hi = 0; hi < 2; ++hi) {
            int row = wm * 64 + mf * 16 + hi * 8 + g;
            float p = 0.0f;
            #pragma unroll
            for (int nt = 0; nt < 8; ++nt) {
                uint32_t b_ = (uint32_t)(row * 128 + (nt * 8 + 2 * tig) * 2);
                uint32_t sw_ = b_ ^ ((b_ >> 3) & 0x70);
                uint32_t u_;
                asm volatile("ld.shared.b32 %0, [%1];" : "=r"(u_) : "r"(aslot + sw_));
                float2 hh = __half22float2(*(__half2*)&u_);
                p += acc[mf][nt][2 * hi + 0] * psum[nt * 2 + 0] * hh.x;
                p += acc[mf][nt][2 * hi + 1] * psum[nt * 2 + 1] * hh.y;
            }
            part[mf * 2 + hi] = p;
        }

    #pragma unroll
    for (int s = 0; s < 8; ++s) {
        part[s] += __shfl_xor_sync(0xffffffffu, part[s], 1);
        part[s] += __shfl_xor_sync(0xffffffffu, part[s], 2);
    }
    float* rowpart = (float*)(dynsmem + RP_OFF);
    if (tig == 0) {
        #pragma unroll
        for (int s = 0; s < 8; ++s) {
            int row = wm * 64 + (s >> 1) * 16 + (s & 1) * 8 + g;
            rowpart[wn * 128 + row] = part[s];
        }
    }
    __syncthreads();

    if (tid < 128) {
        float v = rowpart[tid] + rowpart[128 + tid] + rowpart[256 + tid] + rowpart[384 + tid];
        out[(size_t)blockIdx.x * 128 + tid] = v;
    }
}

extern "C" void kernel_launch(void* const* d_in, const int* in_sizes, int n_in,
                              void* d_out, int out_size) {
    const float* h    = (const float*)d_in[0];  // [4096, 64, 256]
    const float* W    = (const float*)d_in[1];  // [256, 256]
    const float* bias = (const float*)d_in[2];  // [64, 256]
    float* out = (float*)d_out;                 // [4096, 64]

    pack_w_kernel<<<16, 256>>>(W);

    cudaFuncSetAttribute(aspect_attention_kernel,
                         cudaFuncAttributeMaxDynamicSharedMemorySize, SMEM_BYTES);
    aspect_attention_kernel<<<2048, THREADS, SMEM_BYTES>>>(h, bias, out);
}

// round 8
// speedup vs baseline: 1.2120x; 1.0034x over previous
#include <cuda_runtime.h>
#include <cuda_fp16.h>
#include <cstdint>
#include <cstddef>

// AspectAttention round 7: fp16 mma.sync m16n8k16 with MANUAL SOFTWARE PIPELINING.
// 256 thr = 8 warps (2m x 4n), warp tile 64x64 (best traffic config, R4/R5).
// W fragment-packed fp16, smem-resident (128KB). A staged fp16 in 4 FIXED slots
// (64KB) with XOR swizzle; ldmatrix.x4 A double-buffered one k-step ahead; B
// fragments rotate through a 2-deep register buffer, one LDS between MMA groups.
// Phase-2 reads h from the resident fp16 A slots (no global re-read).

#define THREADS   256
#define BOFF      0
#define BBYTES    131072                      // 16 sg x 256 col x 4 tig x 8B
#define AOFF(c)   (BBYTES + (c) * 16384)      // 4 fixed slots: 128 rows x 128B fp16
#define RP_OFF    (BBYTES + 65536)            // rowpart: 512 floats
#define SMEM_BYTES (RP_OFF + 2048)            // ~194 KB

__device__ __half g_Wpack[16 * 256 * 16];     // [sg][col][tig][{b0.lo,b0.hi,b1.lo,b1.hi}]

// ---------------- helpers ----------------
__device__ __forceinline__ float tanh_fast(float x) {
    float y; asm("tanh.approx.f32 %0, %1;" : "=f"(y) : "f"(x)); return y;
}
__device__ __forceinline__ uint32_t pack2(float hi, float lo) {
    uint32_t r; asm("cvt.rn.f16x2.f32 %0, %1, %2;" : "=r"(r) : "f"(hi), "f"(lo)); return r;
}
__device__ __forceinline__ void mma_fp16(float (&c)[4],
                                         uint32_t a0, uint32_t a1, uint32_t a2, uint32_t a3,
                                         uint32_t b0, uint32_t b1) {
    asm volatile(
        "mma.sync.aligned.m16n8k16.row.col.f32.f16.f16.f32 "
        "{%0,%1,%2,%3},{%4,%5,%6,%7},{%8,%9},{%0,%1,%2,%3};"
        : "+f"(c[0]), "+f"(c[1]), "+f"(c[2]), "+f"(c[3])
        : "r"(a0), "r"(a1), "r"(a2), "r"(a3), "r"(b0), "r"(b1));
}
__device__ __forceinline__ void ldmatrix4(uint32_t (&d)[4], uint32_t addr) {
    asm volatile("ldmatrix.sync.aligned.m8n8.x4.shared.b16 {%0,%1,%2,%3}, [%4];"
                 : "=r"(d[0]), "=r"(d[1]), "=r"(d[2]), "=r"(d[3]) : "r"(addr));
}
__device__ __forceinline__ void cp_async16(uint32_t sa, const void* g) {
    asm volatile("cp.async.cg.shared.global [%0], [%1], 16;" :: "r"(sa), "l"(g));
}

// ---------------- W pack: fp16 fragment order (R4, proven) ----------------
__global__ void pack_w_kernel(const float* __restrict__ W) {
    const int s   = blockIdx.x;      // 0..15 (sg)
    const int col = threadIdx.x;     // 0..255
    #pragma unroll
    for (int t = 0; t < 4; ++t) {
        __half* dst = g_Wpack + ((s * 256 + col) * 4 + t) * 4;
        dst[0] = __float2half_rn(W[(16 * s + 2 * t)     * 256 + col]);
        dst[1] = __float2half_rn(W[(16 * s + 2 * t + 1) * 256 + col]);
        dst[2] = __float2half_rn(W[(16 * s + 2 * t + 8) * 256 + col]);
        dst[3] = __float2half_rn(W[(16 * s + 2 * t + 9) * 256 + col]);
    }
}

// ---------------- main kernel ----------------
__global__ __launch_bounds__(THREADS, 1)
void aspect_attention_kernel(const float* __restrict__ h,
                             const float* __restrict__ bias,
                             float* __restrict__ out) {
    extern __shared__ __align__(16) char dynsmem[];
    const uint32_t smem_u32 = (uint32_t)__cvta_generic_to_shared(dynsmem);

    const int tid  = threadIdx.x;
    const int w    = tid >> 5;
    const int lane = tid & 31;
    const int g    = lane >> 2;
    const int tig  = lane & 3;
    const int wm   = w & 1;        // row block: wm*64
    const int wn   = w >> 1;       // col block: wn*64

    // ldmatrix per-thread constants (R5, proven)
    const int arow0  = wm * 64 + (lane & 7) + ((lane >> 3) & 1) * 8;  // + mf*16
    const uint32_t X  = ((uint32_t)(lane & 7)) << 4;
    const uint32_t kL = ((uint32_t)((lane >> 4) & 1)) * 16;

    // LDG/STS constants (R5, proven)
    const int srow  = tid >> 4;      // + j*16
    const int squad = tid & 15;

    const float* hb = h + (size_t)blockIdx.x * (128 * 256);

    float acc[4][8][4];
    #pragma unroll
    for (int mf = 0; mf < 4; ++mf)
        #pragma unroll
        for (int nt = 0; nt < 8; ++nt)
            #pragma unroll
            for (int i = 0; i < 4; ++i) acc[mf][nt][i] = 0.0f;

    float4 buf[8];

    #define LDG_CHUNK(c) do {                                                     \
        const float* src_ = hb + (c) * 64;                                        \
        _Pragma("unroll")                                                         \
        for (int j = 0; j < 8; ++j)                                               \
            buf[j] = *(const float4*)(src_ + (srow + j * 16) * 256 + squad * 4);  \
    } while (0)

    #define STS_CHUNK(c) do {                                                     \
        uint32_t base_ = smem_u32 + AOFF(c);                                      \
        _Pragma("unroll")                                                         \
        for (int j = 0; j < 8; ++j) {                                             \
            uint32_t b_ = (uint32_t)((srow + j * 16) * 128 + squad * 8);          \
            uint32_t sw_ = b_ ^ ((b_ >> 3) & 0x70);                               \
            uint32_t u0_ = pack2(buf[j].y, buf[j].x);                             \
            uint32_t u1_ = pack2(buf[j].w, buf[j].z);                             \
            asm volatile("st.shared.v2.u32 [%0], {%1,%2};"                        \
                         :: "r"(base_ + sw_), "r"(u0_), "r"(u1_));                \
        }                                                                         \
    } while (0)

    // pipeline registers
    uint32_t A0[4][4], A1[4][4];
    uint32_t Bb[2][2];

    #define LOAD_A(slot, ss, A_) do {                                             \
        uint32_t ab_ = smem_u32 + AOFF(slot);                                     \
        _Pragma("unroll")                                                         \
        for (int mf = 0; mf < 4; ++mf) {                                          \
            uint32_t b_ = (uint32_t)((arow0 + mf * 16) * 128) + kL + (ss) * 32;   \
            ldmatrix4(A_[mf], ab_ + (b_ ^ X));                                    \
        }                                                                         \
    } while (0)

    #define LDB(sg, nt, p) do {                                                   \
        uint32_t ba_ = smem_u32 + BOFF +                                          \
            (uint32_t)(((((sg) * 256 + wn * 64 + (nt) * 8 + g) * 4) + tig) * 8);  \
        asm volatile("ld.shared.v2.u32 {%0,%1}, [%2];"                            \
                     : "=r"(Bb[p][0]), "=r"(Bb[p][1]) : "r"(ba_));                \
    } while (0)

    // One k16 step: prefetch B one nt ahead; at nt==7 prefetch first B of next sg.
    #define NTLOOP(sg, A_, last) do {                                             \
        _Pragma("unroll")                                                         \
        for (int nt = 0; nt < 8; ++nt) {                                          \
            if (nt < 7)        LDB((sg), nt + 1, (nt + 1) & 1);                   \
            else if (!(last))  LDB((sg) + 1, 0, 0);                               \
            _Pragma("unroll")                                                     \
            for (int mf = 0; mf < 4; ++mf)                                        \
                mma_fp16(acc[mf][nt],                                             \
                         A_[mf][0], A_[mf][1], A_[mf][2], A_[mf][3],              \
                         Bb[nt & 1][0], Bb[nt & 1][1]);                           \
        }                                                                         \
    } while (0)

    // Chunk body: entering with A0 = A(sg=4c), Bb[0] = B(4c, 0).
    #define CHUNK_BODY(c) do {                                                    \
        LOAD_A((c), 1, A1);  NTLOOP(4 * (c) + 0, A0, 0);                          \
        LOAD_A((c), 2, A0);  NTLOOP(4 * (c) + 1, A1, 0);                          \
        LOAD_A((c), 3, A1);  NTLOOP(4 * (c) + 2, A0, 0);                          \
                             NTLOOP(4 * (c) + 3, A1, ((c) == 3));                 \
    } while (0)

    // ---- prologue: B resident via cp.async; chunk0 LDG->STS; chunk1 LDG ----
    {
        const char* bsrc = (const char*)g_Wpack;
        #pragma unroll
        for (int it = 0; it < 32; ++it) {
            int i_ = it * THREADS + tid;
            cp_async16(smem_u32 + BOFF + i_ * 16, bsrc + i_ * 16);
        }
        asm volatile("cp.async.commit_group;");
    }
    LDG_CHUNK(0);
    STS_CHUNK(0);
    LDG_CHUNK(1);
    asm volatile("cp.async.wait_group 0;");
    __syncthreads();

    // ---- pipelined main loop (4 chunks, fixed slots, 1 barrier each) ----
    LOAD_A(0, 0, A0);
    LDB(0, 0, 0);
    CHUNK_BODY(0);

    STS_CHUNK(1); LDG_CHUNK(2);
    __syncthreads();
    LOAD_A(1, 0, A0);          // Bb[0] already holds B(4,0)
    CHUNK_BODY(1);

    STS_CHUNK(2); LDG_CHUNK(3);
    __syncthreads();
    LOAD_A(2, 0, A0);
    CHUNK_BODY(2);

    STS_CHUNK(3);
    __syncthreads();
    LOAD_A(3, 0, A0);
    CHUNK_BODY(3);

    // ---- epilogue phase 1: e = exp(tanh(s + bias)); intra-warp column sums ----
    float psum[16];
    #pragma unroll
    for (int j = 0; j < 16; ++j) psum[j] = 0.0f;

    #pragma unroll
    for (int mf = 0; mf < 4; ++mf)
        #pragma unroll
        for (int hi = 0; hi < 2; ++hi) {
            int row = wm * 64 + mf * 16 + hi * 8 + g;
            const float* brow = bias + (row & 63) * 256 + wn * 64 + 2 * tig;
            #pragma unroll
            for (int nt = 0; nt < 8; ++nt) {
                float2 bb = *(const float2*)(brow + nt * 8);
                float e0 = __expf(tanh_fast(acc[mf][nt][2 * hi + 0] + bb.x));
                float e1 = __expf(tanh_fast(acc[mf][nt][2 * hi + 1] + bb.y));
                acc[mf][nt][2 * hi + 0] = e0;
                acc[mf][nt][2 * hi + 1] = e1;
                psum[nt * 2 + 0] += e0;
                psum[nt * 2 + 1] += e1;
            }
        }

    #pragma unroll
    for (int j = 0; j < 16; ++j) {
        psum[j] += __shfl_xor_sync(0xffffffffu, psum[j], 4);
        psum[j] += __shfl_xor_sync(0xffffffffu, psum[j], 8);
        psum[j] += __shfl_xor_sync(0xffffffffu, psum[j], 16);
        psum[j] = 1.0f / psum[j];            // inv(colsum)
    }

    // ---- phase 2: out[row] = sum_col e * inv * h (h from resident fp16 slots) ----
    const uint32_t aslot = smem_u32 + AOFF(wn);     // warp's 64-col strip lives in slot wn
    float part[8];
    #pragma unroll
    for (int mf = 0; mf < 4; ++mf)
        #pragma unroll
        for (int hi = 0; hi < 2; ++hi) {
            int row = wm * 64 + mf * 16 + hi * 8 + g;
            float p = 0.0f;
            #pragma unroll
            for (int nt = 0; nt < 8; ++nt) {
                uint32_t b_ = (uint32_t)(row * 128 + (nt * 8 + 2 * tig) * 2);
                uint32_t sw_ = b_ ^ ((b_ >> 3) & 0x70);
                uint32_t u_;
                asm volatile("ld.shared.b32 %0, [%1];" : "=r"(u_) : "r"(aslot + sw_));
                float2 hh = __half22float2(*(__half2*)&u_);
                p += acc[mf][nt][2 * hi + 0] * psum[nt * 2 + 0] * hh.x;
                p += acc[mf][nt][2 * hi + 1] * psum[nt * 2 + 1] * hh.y;
            }
            part[mf * 2 + hi] = p;
        }

    #pragma unroll
    for (int s = 0; s < 8; ++s) {
        part[s] += __shfl_xor_sync(0xffffffffu, part[s], 1);
        part[s] += __shfl_xor_sync(0xffffffffu, part[s], 2);
    }
    float* rowpart = (float*)(dynsmem + RP_OFF);
    if (tig == 0) {
        #pragma unroll
        for (int s = 0; s < 8; ++s) {
            int row = wm * 64 + (s >> 1) * 16 + (s & 1) * 8 + g;
            rowpart[wn * 128 + row] = part[s];
        }
    }
    __syncthreads();

    if (tid < 128) {
        float v = rowpart[tid] + rowpart[128 + tid] + rowpart[256 + tid] + rowpart[384 + tid];
        out[(size_t)blockIdx.x * 128 + tid] = v;
    }
}

extern "C" void kernel_launch(void* const* d_in, const int* in_sizes, int n_in,
                              void* d_out, int out_size) {
    const float* h    = (const float*)d_in[0];  // [4096, 64, 256]
    const float* W    = (const float*)d_in[1];  // [256, 256]
    const float* bias = (const float*)d_in[2];  // [64, 256]
    float* out = (float*)d_out;                 // [4096, 64]

    pack_w_kernel<<<16, 256>>>(W);

    cudaFuncSetAttribute(aspect_attention_kernel,
                         cudaFuncAttributeMaxDynamicSharedMemorySize, SMEM_BYTES);
    aspect_attention_kernel<<<2048, THREADS, SMEM_BYTES>>>(h, bias, out);
}

// round 13
// speedup vs baseline: 1.2256x; 1.0113x over previous
#include <cuda_runtime.h>
#include <cuda_fp16.h>
#include <cstdint>
#include <cstddef>

// AspectAttention round 8: fp16 mma.sync, software-pipelined, B in uint4 k-pairs.
// 256 thr = 8 warps (2m x 4n), warp tile 64x64. W fragment-packed fp16 as uint4
// (one LDS.128 = B frags for 2 consecutive k16-steps -> feeds 8 HMMAs), smem-resident.
// A staged fp16 in 4 fixed slots (XOR swizzle, ldmatrix.x4). Epilogue exp via
// ex2.approx.f16x2 (one MUFU per value-pair); tanh stays f32. Phase-2 h from smem.

#define THREADS   256
#define BOFF      0
#define BBYTES    131072                      // 8 pairs x 256 col x 4 tig x 16B
#define AOFF(c)   (BBYTES + (c) * 16384)      // 4 fixed slots: 128 rows x 128B fp16
#define RP_OFF    (BBYTES + 65536)            // rowpart: 512 floats
#define SMEM_BYTES (RP_OFF + 2048)            // ~194 KB

__device__ __half g_Wpack[8 * 256 * 4 * 8];   // [pair][col][tig][8 halves = uint4]

// ---------------- helpers ----------------
__device__ __forceinline__ float tanh_fast(float x) {
    float y; asm("tanh.approx.f32 %0, %1;" : "=f"(y) : "f"(x)); return y;
}
__device__ __forceinline__ uint32_t pack2(float hi, float lo) {
    uint32_t r; asm("cvt.rn.f16x2.f32 %0, %1, %2;" : "=r"(r) : "f"(hi), "f"(lo)); return r;
}
__device__ __forceinline__ void mma_fp16(float (&c)[4],
                                         uint32_t a0, uint32_t a1, uint32_t a2, uint32_t a3,
                                         uint32_t b0, uint32_t b1) {
    asm volatile(
        "mma.sync.aligned.m16n8k16.row.col.f32.f16.f16.f32 "
        "{%0,%1,%2,%3},{%4,%5,%6,%7},{%8,%9},{%0,%1,%2,%3};"
        : "+f"(c[0]), "+f"(c[1]), "+f"(c[2]), "+f"(c[3])
        : "r"(a0), "r"(a1), "r"(a2), "r"(a3), "r"(b0), "r"(b1));
}
__device__ __forceinline__ void ldmatrix4(uint32_t (&d)[4], uint32_t addr) {
    asm volatile("ldmatrix.sync.aligned.m8n8.x4.shared.b16 {%0,%1,%2,%3}, [%4];"
                 : "=r"(d[0]), "=r"(d[1]), "=r"(d[2]), "=r"(d[3]) : "r"(addr));
}
__device__ __forceinline__ void cp_async16(uint32_t sa, const void* g) {
    asm volatile("cp.async.cg.shared.global [%0], [%1], 16;" :: "r"(sa), "l"(g));
}

// ---------------- W pack: uint4 = B frags for k16-step pair (2p, 2p+1) ----------
__global__ void pack_w_kernel(const float* __restrict__ W) {
    const int p   = blockIdx.x;      // pair 0..7
    const int col = threadIdx.x;     // 0..255
    #pragma unroll
    for (int t = 0; t < 4; ++t) {
        __half* dst = g_Wpack + (((p * 256 + col) * 4 + t) * 8);
        const int k0 = 32 * p + 2 * t;        // sg even = 2p
        dst[0] = __float2half_rn(W[(k0)     * 256 + col]);
        dst[1] = __float2half_rn(W[(k0 + 1) * 256 + col]);
        dst[2] = __float2half_rn(W[(k0 + 8) * 256 + col]);
        dst[3] = __float2half_rn(W[(k0 + 9) * 256 + col]);
        const int k1 = k0 + 16;               // sg odd = 2p+1
        dst[4] = __float2half_rn(W[(k1)     * 256 + col]);
        dst[5] = __float2half_rn(W[(k1 + 1) * 256 + col]);
        dst[6] = __float2half_rn(W[(k1 + 8) * 256 + col]);
        dst[7] = __float2half_rn(W[(k1 + 9) * 256 + col]);
    }
}

// ---------------- main kernel ----------------
__global__ __launch_bounds__(THREADS, 1)
void aspect_attention_kernel(const float* __restrict__ h,
                             const float* __restrict__ bias,
                             float* __restrict__ out) {
    extern __shared__ __align__(16) char dynsmem[];
    const uint32_t smem_u32 = (uint32_t)__cvta_generic_to_shared(dynsmem);

    const int tid  = threadIdx.x;
    const int w    = tid >> 5;
    const int lane = tid & 31;
    const int g    = lane >> 2;
    const int tig  = lane & 3;
    const int wm   = w & 1;        // row block: wm*64
    const int wn   = w >> 1;       // col block: wn*64

    // ldmatrix per-thread constants (proven)
    const int arow0  = wm * 64 + (lane & 7) + ((lane >> 3) & 1) * 8;  // + mf*16
    const uint32_t X  = ((uint32_t)(lane & 7)) << 4;
    const uint32_t kL = ((uint32_t)((lane >> 4) & 1)) * 16;

    // LDG/STS constants (proven)
    const int srow  = tid >> 4;      // + j*16
    const int squad = tid & 15;

    const float* hb = h + (size_t)blockIdx.x * (128 * 256);

    float acc[4][8][4];
    #pragma unroll
    for (int mf = 0; mf < 4; ++mf)
        #pragma unroll
        for (int nt = 0; nt < 8; ++nt)
            #pragma unroll
            for (int i = 0; i < 4; ++i) acc[mf][nt][i] = 0.0f;

    float4 buf[8];

    #define LDG_CHUNK(c) do {                                                     \
        const float* src_ = hb + (c) * 64;                                        \
        _Pragma("unroll")                                                         \
        for (int j = 0; j < 8; ++j)                                               \
            buf[j] = *(const float4*)(src_ + (srow + j * 16) * 256 + squad * 4);  \
    } while (0)

    #define STS_CHUNK(c) do {                                                     \
        uint32_t base_ = smem_u32 + AOFF(c);                                      \
        _Pragma("unroll")                                                         \
        for (int j = 0; j < 8; ++j) {                                             \
            uint32_t b_ = (uint32_t)((srow + j * 16) * 128 + squad * 8);          \
            uint32_t sw_ = b_ ^ ((b_ >> 3) & 0x70);                               \
            uint32_t u0_ = pack2(buf[j].y, buf[j].x);                             \
            uint32_t u1_ = pack2(buf[j].w, buf[j].z);                             \
            asm volatile("st.shared.v2.u32 [%0], {%1,%2};"                        \
                         :: "r"(base_ + sw_), "r"(u0_), "r"(u1_));                \
        }                                                                         \
    } while (0)

    // pipeline registers
    uint32_t A0[4][4], A1[4][4];
    uint32_t Bb[2][4];

    #define LOAD_A(slot, ss, A_) do {                                             \
        uint32_t ab_ = smem_u32 + AOFF(slot);                                     \
        _Pragma("unroll")                                                         \
        for (int mf = 0; mf < 4; ++mf) {                                          \
            uint32_t b_ = (uint32_t)((arow0 + mf * 16) * 128) + kL + (ss) * 32;   \
            ldmatrix4(A_[mf], ab_ + (b_ ^ X));                                    \
        }                                                                         \
    } while (0)

    #define LDB4(p, nt, slot) do {                                                \
        uint32_t ba_ = smem_u32 + BOFF +                                          \
            (uint32_t)(((((p) * 256 + wn * 64 + (nt) * 8 + g) * 4) + tig) * 16);  \
        asm volatile("ld.shared.v4.u32 {%0,%1,%2,%3}, [%4];"                      \
                     : "=r"(Bb[slot][0]), "=r"(Bb[slot][1]),                      \
                       "=r"(Bb[slot][2]), "=r"(Bb[slot][3]) : "r"(ba_));          \
    } while (0)

    // One pair of k16 steps: Bb[cur] holds B4(p, nt); prefetch one group ahead.
    // 8 HMMAs per LDS.128 -> prefetch window ~32 cyc >= LDS latency.
    #define PAIR_BODY(p, last) do {                                               \
        _Pragma("unroll")                                                         \
        for (int nt = 0; nt < 8; ++nt) {                                          \
            if (nt < 7)        LDB4((p), nt + 1, (nt + 1) & 1);                   \
            else if (!(last))  LDB4((p) + 1, 0, 0);                               \
            _Pragma("unroll")                                                     \
            for (int mf = 0; mf < 4; ++mf)                                        \
                mma_fp16(acc[mf][nt], A0[mf][0], A0[mf][1], A0[mf][2], A0[mf][3], \
                         Bb[nt & 1][0], Bb[nt & 1][1]);                           \
            _Pragma("unroll")                                                     \
            for (int mf = 0; mf < 4; ++mf)                                        \
                mma_fp16(acc[mf][nt], A1[mf][0], A1[mf][1], A1[mf][2], A1[mf][3], \
                         Bb[nt & 1][2], Bb[nt & 1][3]);                           \
        }                                                                         \
    } while (0)

    // Chunk c: pairs 2c (ss 0,1) and 2c+1 (ss 2,3) from fixed slot c.
    #define CHUNK_BODY(c) do {                                                    \
        LOAD_A((c), 0, A0); LOAD_A((c), 1, A1);                                   \
        PAIR_BODY(2 * (c), 0);                                                    \
        LOAD_A((c), 2, A0); LOAD_A((c), 3, A1);                                   \
        PAIR_BODY(2 * (c) + 1, ((c) == 3));                                       \
    } while (0)

    // ---- prologue: B resident via cp.async; chunk0 LDG->STS; chunk1 LDG ----
    {
        const char* bsrc = (const char*)g_Wpack;
        #pragma unroll
        for (int it = 0; it < 32; ++it) {
            int i_ = it * THREADS + tid;
            cp_async16(smem_u32 + BOFF + i_ * 16, bsrc + i_ * 16);
        }
        asm volatile("cp.async.commit_group;");
    }
    LDG_CHUNK(0);
    STS_CHUNK(0);
    LDG_CHUNK(1);
    asm volatile("cp.async.wait_group 0;");
    __syncthreads();

    // ---- pipelined main loop ----
    LDB4(0, 0, 0);
    CHUNK_BODY(0);

    STS_CHUNK(1); LDG_CHUNK(2);
    __syncthreads();
    CHUNK_BODY(1);

    STS_CHUNK(2); LDG_CHUNK(3);
    __syncthreads();
    CHUNK_BODY(2);

    STS_CHUNK(3);
    __syncthreads();
    CHUNK_BODY(3);

    // ---- epilogue phase 1: e = exp(tanh(s + bias)) via ex2.f16x2; column sums ----
    const float LOG2E = 1.4426950408889634f;
    float psum[16];
    #pragma unroll
    for (int j = 0; j < 16; ++j) psum[j] = 0.0f;

    #pragma unroll
    for (int mf = 0; mf < 4; ++mf)
        #pragma unroll
        for (int hi = 0; hi < 2; ++hi) {
            int row = wm * 64 + mf * 16 + hi * 8 + g;
            const float* brow = bias + (row & 63) * 256 + wn * 64 + 2 * tig;
            #pragma unroll
            for (int nt = 0; nt < 8; ++nt) {
                float2 bb = *(const float2*)(brow + nt * 8);
                float t0 = tanh_fast(acc[mf][nt][2 * hi + 0] + bb.x) * LOG2E;
                float t1 = tanh_fast(acc[mf][nt][2 * hi + 1] + bb.y) * LOG2E;
                uint32_t up = pack2(t1, t0);
                uint32_t ep;
                asm("ex2.approx.f16x2 %0, %1;" : "=r"(ep) : "r"(up));
                float2 e2 = __half22float2(*(__half2*)&ep);
                acc[mf][nt][2 * hi + 0] = e2.x;
                acc[mf][nt][2 * hi + 1] = e2.y;
                psum[nt * 2 + 0] += e2.x;
                psum[nt * 2 + 1] += e2.y;
            }
        }

    #pragma unroll
    for (int j = 0; j < 16; ++j) {
        psum[j] += __shfl_xor_sync(0xffffffffu, psum[j], 4);
        psum[j] += __shfl_xor_sync(0xffffffffu, psum[j], 8);
        psum[j] += __shfl_xor_sync(0xffffffffu, psum[j], 16);
        psum[j] = 1.0f / psum[j];            // inv(colsum)
    }

    // ---- phase 2: out[row] = sum_col e * inv * h (h from resident fp16 slots) ----
    const uint32_t aslot = smem_u32 + AOFF(wn);     // warp's 64-col strip lives in slot wn
    float part[8];
    #pragma unroll
    for (int mf = 0; mf < 4; ++mf)
        #pragma unroll
        for (int hi = 0; hi < 2; ++hi) {
            int row = wm * 64 + mf * 16 + hi * 8 + g;
            float p = 0.0f;
            #pragma unroll
            for (int nt = 0; nt < 8; ++nt) {
                uint32_t b_ = (uint32_t)(row * 128 + (nt * 8 + 2 * tig) * 2);
                uint32_t sw_ = b_ ^ ((b_ >> 3) & 0x70);
                uint32_t u_;
                asm volatile("ld.shared.b32 %0, [%1];" : "=r"(u_) : "r"(aslot + sw_));
                float2 hh = __half22float2(*(__half2*)&u_);
                p += acc[mf][nt][2 * hi + 0] * psum[nt * 2 + 0] * hh.x;
                p += acc[mf][nt][2 * hi + 1] * psum[nt * 2 + 1] * hh.y;
            }
            part[mf * 2 + hi] = p;
        }

    #pragma unroll
    for (int s = 0; s < 8; ++s) {
        part[s] += __shfl_xor_sync(0xffffffffu, part[s], 1);
        part[s] += __shfl_xor_sync(0xffffffffu, part[s], 2);
    }
    float* rowpart = (float*)(dynsmem + RP_OFF);
    if (tig == 0) {
        #pragma unroll
        for (int s = 0; s < 8; ++s) {
            int row = wm * 64 + (s >> 1) * 16 + (s & 1) * 8 + g;
            rowpart[wn * 128 + row] = part[s];
        }
    }
    __syncthreads();

    if (tid < 128) {
        float v = rowpart[tid] + rowpart[128 + tid] + rowpart[256 + tid] + rowpart[384 + tid];
        out[(size_t)blockIdx.x * 128 + tid] = v;
    }
}

extern "C" void kernel_launch(void* const* d_in, const int* in_sizes, int n_in,
                              void* d_out, int out_size) {
    const float* h    = (const float*)d_in[0];  // [4096, 64, 256]
    const float* W    = (const float*)d_in[1];  // [256, 256]
    const float* bias = (const float*)d_in[2];  // [64, 256]
    float* out = (float*)d_out;                 // [4096, 64]

    pack_w_kernel<<<8, 256>>>(W);

    cudaFuncSetAttribute(aspect_attention_kernel,
                         cudaFuncAttributeMaxDynamicSharedMemorySize, SMEM_BYTES);
    aspect_attention_kernel<<<2048, THREADS, SMEM_BYTES>>>(h, bias, out);
}

// round 15
// speedup vs baseline: 1.2287x; 1.0025x over previous
#include <cuda_runtime.h>
#include <cuda_fp16.h>
#include <cstdint>
#include <cstddef>

// AspectAttention round 9: R8 + fragment-packed bias (kills ~4K scattered-LDG
// wavefronts per CTA in the epilogue).
// 256 thr = 8 warps (2m x 4n), warp tile 64x64, fp16 mma.sync m16n8k16.
// W fragment-packed fp16 uint4 (1 LDS.128 = 2 k-steps = 8 HMMAs), smem-resident.
// A staged fp16 in 4 fixed slots (XOR swizzle, ldmatrix.x4), software-pipelined.
// Bias fragment-packed half2 in smem: dense 1-wavefront LDS in epilogue.
// exp via ex2.approx.f16x2; phase-2 h from resident fp16 A slots.

#define THREADS   256
#define BOFF      0
#define BBYTES    131072                      // 8 pairs x 256 col x 4 tig x 16B
#define AOFF(c)   (BBYTES + (c) * 16384)      // 4 fixed slots: 128 rows x 128B fp16
#define RP_OFF    (BBYTES + 65536)            // rowpart: 512 floats
#define BIAS_OFF  (RP_OFF + 2048)             // bias pack: 8192 x u32 = 32KB
#define SMEM_BYTES (BIAS_OFF + 32768)         // 231,424 B (< 227KB cap)

__device__ __half g_Wpack[8 * 256 * 4 * 8];   // [pair][col][tig][8 halves = uint4]
__device__ uint32_t g_biaspack[4 * 64 * 32];  // [wn][j=mf*16+hi*8+nt][lane] half2

// ---------------- helpers ----------------
__device__ __forceinline__ float tanh_fast(float x) {
    float y; asm("tanh.approx.f32 %0, %1;" : "=f"(y) : "f"(x)); return y;
}
__device__ __forceinline__ uint32_t pack2(float hi, float lo) {
    uint32_t r; asm("cvt.rn.f16x2.f32 %0, %1, %2;" : "=r"(r) : "f"(hi), "f"(lo)); return r;
}
__device__ __forceinline__ void mma_fp16(float (&c)[4],
                                         uint32_t a0, uint32_t a1, uint32_t a2, uint32_t a3,
                                         uint32_t b0, uint32_t b1) {
    asm volatile(
        "mma.sync.aligned.m16n8k16.row.col.f32.f16.f16.f32 "
        "{%0,%1,%2,%3},{%4,%5,%6,%7},{%8,%9},{%0,%1,%2,%3};"
        : "+f"(c[0]), "+f"(c[1]), "+f"(c[2]), "+f"(c[3])
        : "r"(a0), "r"(a1), "r"(a2), "r"(a3), "r"(b0), "r"(b1));
}
__device__ __forceinline__ void ldmatrix4(uint32_t (&d)[4], uint32_t addr) {
    asm volatile("ldmatrix.sync.aligned.m8n8.x4.shared.b16 {%0,%1,%2,%3}, [%4];"
                 : "=r"(d[0]), "=r"(d[1]), "=r"(d[2]), "=r"(d[3]) : "r"(addr));
}
__device__ __forceinline__ void cp_async16(uint32_t sa, const void* g) {
    asm volatile("cp.async.cg.shared.global [%0], [%1], 16;" :: "r"(sa), "l"(g));
}

// ---------------- W pack: uint4 = B frags for k16-step pair (2p, 2p+1) ----------
__global__ void pack_w_kernel(const float* __restrict__ W) {
    const int p   = blockIdx.x;      // pair 0..7
    const int col = threadIdx.x;     // 0..255
    #pragma unroll
    for (int t = 0; t < 4; ++t) {
        __half* dst = g_Wpack + (((p * 256 + col) * 4 + t) * 8);
        const int k0 = 32 * p + 2 * t;
        dst[0] = __float2half_rn(W[(k0)     * 256 + col]);
        dst[1] = __float2half_rn(W[(k0 + 1) * 256 + col]);
        dst[2] = __float2half_rn(W[(k0 + 8) * 256 + col]);
        dst[3] = __float2half_rn(W[(k0 + 9) * 256 + col]);
        const int k1 = k0 + 16;
        dst[4] = __float2half_rn(W[(k1)     * 256 + col]);
        dst[5] = __float2half_rn(W[(k1 + 1) * 256 + col]);
        dst[6] = __float2half_rn(W[(k1 + 8) * 256 + col]);
        dst[7] = __float2half_rn(W[(k1 + 9) * 256 + col]);
    }
}

// ---------------- bias pack: [wn][j][lane] = half2(bias[n][col], bias[n][col+1])
// n = mf*16 + hi*8 + g, col = wn*64 + nt*8 + 2*tig, j = mf*16 + hi*8 + nt.
__global__ void pack_bias_kernel(const float* __restrict__ bias) {
    int idx  = blockIdx.x * 256 + threadIdx.x;   // 0..8191
    int wn   = idx >> 11;
    int j    = (idx >> 5) & 63;
    int lane = idx & 31;
    int mf = j >> 4, hi = (j >> 3) & 1, nt = j & 7;
    int g = lane >> 2, tig = lane & 3;
    int n   = mf * 16 + hi * 8 + g;
    int col = wn * 64 + nt * 8 + 2 * tig;
    __half2 v = __floats2half2_rn(bias[n * 256 + col], bias[n * 256 + col + 1]);
    g_biaspack[idx] = *(uint32_t*)&v;
}

// ---------------- main kernel ----------------
__global__ __launch_bounds__(THREADS, 1)
void aspect_attention_kernel(const float* __restrict__ h,
                             float* __restrict__ out) {
    extern __shared__ __align__(16) char dynsmem[];
    const uint32_t smem_u32 = (uint32_t)__cvta_generic_to_shared(dynsmem);

    const int tid  = threadIdx.x;
    const int w    = tid >> 5;
    const int lane = tid & 31;
    const int g    = lane >> 2;
    const int tig  = lane & 3;
    const int wm   = w & 1;        // row block: wm*64
    const int wn   = w >> 1;       // col block: wn*64

    const int arow0  = wm * 64 + (lane & 7) + ((lane >> 3) & 1) * 8;  // + mf*16
    const uint32_t X  = ((uint32_t)(lane & 7)) << 4;
    const uint32_t kL = ((uint32_t)((lane >> 4) & 1)) * 16;

    const int srow  = tid >> 4;      // + j*16
    const int squad = tid & 15;

    const float* hb = h + (size_t)blockIdx.x * (128 * 256);

    float acc[4][8][4];
    #pragma unroll
    for (int mf = 0; mf < 4; ++mf)
        #pragma unroll
        for (int nt = 0; nt < 8; ++nt)
            #pragma unroll
            for (int i = 0; i < 4; ++i) acc[mf][nt][i] = 0.0f;

    float4 buf[8];

    #define LDG_CHUNK(c) do {                                                     \
        const float* src_ = hb + (c) * 64;                                        \
        _Pragma("unroll")                                                         \
        for (int j = 0; j < 8; ++j)                                               \
            buf[j] = *(const float4*)(src_ + (srow + j * 16) * 256 + squad * 4);  \
    } while (0)

    #define STS_CHUNK(c) do {                                                     \
        uint32_t base_ = smem_u32 + AOFF(c);                                      \
        _Pragma("unroll")                                                         \
        for (int j = 0; j < 8; ++j) {                                             \
            uint32_t b_ = (uint32_t)((srow + j * 16) * 128 + squad * 8);          \
            uint32_t sw_ = b_ ^ ((b_ >> 3) & 0x70);                               \
            uint32_t u0_ = pack2(buf[j].y, buf[j].x);                             \
            uint32_t u1_ = pack2(buf[j].w, buf[j].z);                             \
            asm volatile("st.shared.v2.u32 [%0], {%1,%2};"                        \
                         :: "r"(base_ + sw_), "r"(u0_), "r"(u1_));                \
        }                                                                         \
    } while (0)

    uint32_t A0[4][4], A1[4][4];
    uint32_t Bb[2][4];

    #define LOAD_A(slot, ss, A_) do {                                             \
        uint32_t ab_ = smem_u32 + AOFF(slot);                                     \
        _Pragma("unroll")                                                         \
        for (int mf = 0; mf < 4; ++mf) {                                          \
            uint32_t b_ = (uint32_t)((arow0 + mf * 16) * 128) + kL + (ss) * 32;   \
            ldmatrix4(A_[mf], ab_ + (b_ ^ X));                                    \
        }                                                                         \
    } while (0)

    #define LDB4(p, nt, slot) do {                                                \
        uint32_t ba_ = smem_u32 + BOFF +                                          \
            (uint32_t)(((((p) * 256 + wn * 64 + (nt) * 8 + g) * 4) + tig) * 16);  \
        asm volatile("ld.shared.v4.u32 {%0,%1,%2,%3}, [%4];"                      \
                     : "=r"(Bb[slot][0]), "=r"(Bb[slot][1]),                      \
                       "=r"(Bb[slot][2]), "=r"(Bb[slot][3]) : "r"(ba_));          \
    } while (0)

    #define PAIR_BODY(p, last) do {                                               \
        _Pragma("unroll")                                                         \
        for (int nt = 0; nt < 8; ++nt) {                                          \
            if (nt < 7)        LDB4((p), nt + 1, (nt + 1) & 1);                   \
            else if (!(last))  LDB4((p) + 1, 0, 0);                               \
            _Pragma("unroll")                                                     \
            for (int mf = 0; mf < 4; ++mf)                                        \
                mma_fp16(acc[mf][nt], A0[mf][0], A0[mf][1], A0[mf][2], A0[mf][3], \
                         Bb[nt & 1][0], Bb[nt & 1][1]);                           \
            _Pragma("unroll")                                                     \
            for (int mf = 0; mf < 4; ++mf)                                        \
                mma_fp16(acc[mf][nt], A1[mf][0], A1[mf][1], A1[mf][2], A1[mf][3], \
                         Bb[nt & 1][2], Bb[nt & 1][3]);                           \
        }                                                                         \
    } while (0)

    #define CHUNK_BODY(c) do {                                                    \
        LOAD_A((c), 0, A0); LOAD_A((c), 1, A1);                                   \
        PAIR_BODY(2 * (c), 0);                                                    \
        LOAD_A((c), 2, A0); LOAD_A((c), 3, A1);                                   \
        PAIR_BODY(2 * (c) + 1, ((c) == 3));                                       \
    } while (0)

    // ---- prologue: B + bias pack resident via cp.async; chunk0 LDG->STS ----
    {
        const char* bsrc = (const char*)g_Wpack;
        #pragma unroll
        for (int it = 0; it < 32; ++it) {
            int i_ = it * THREADS + tid;
            cp_async16(smem_u32 + BOFF + i_ * 16, bsrc + i_ * 16);
        }
        const char* psrc = (const char*)g_biaspack;
        #pragma unroll
        for (int it = 0; it < 8; ++it) {
            int i_ = it * THREADS + tid;
            cp_async16(smem_u32 + BIAS_OFF + i_ * 16, psrc + i_ * 16);
        }
        asm volatile("cp.async.commit_group;");
    }
    LDG_CHUNK(0);
    STS_CHUNK(0);
    LDG_CHUNK(1);
    asm volatile("cp.async.wait_group 0;");
    __syncthreads();

    // ---- pipelined main loop ----
    LDB4(0, 0, 0);
    CHUNK_BODY(0);

    STS_CHUNK(1); LDG_CHUNK(2);
    __syncthreads();
    CHUNK_BODY(1);

    STS_CHUNK(2); LDG_CHUNK(3);
    __syncthreads();
    CHUNK_BODY(2);

    STS_CHUNK(3);
    __syncthreads();
    CHUNK_BODY(3);

    // ---- epilogue phase 1: e = exp(tanh(s + bias)); column sums ----
    const float LOG2E = 1.4426950408889634f;
    const uint32_t bias_base = smem_u32 + BIAS_OFF + (uint32_t)(((wn * 64) * 32 + lane) * 4);
    float psum[16];
    #pragma unroll
    for (int j = 0; j < 16; ++j) psum[j] = 0.0f;

    #pragma unroll
    for (int mf = 0; mf < 4; ++mf)
        #pragma unroll
        for (int hi = 0; hi < 2; ++hi) {
            #pragma unroll
            for (int nt = 0; nt < 8; ++nt) {
                uint32_t bu;
                asm volatile("ld.shared.b32 %0, [%1];" : "=r"(bu)
                             : "r"(bias_base + (uint32_t)((mf * 16 + hi * 8 + nt) * 128)));
                float2 bb = __half22float2(*(__half2*)&bu);
                float t0 = tanh_fast(acc[mf][nt][2 * hi + 0] + bb.x) * LOG2E;
                float t1 = tanh_fast(acc[mf][nt][2 * hi + 1] + bb.y) * LOG2E;
                uint32_t up = pack2(t1, t0);
                uint32_t ep;
                asm("ex2.approx.f16x2 %0, %1;" : "=r"(ep) : "r"(up));
                float2 e2 = __half22float2(*(__half2*)&ep);
                acc[mf][nt][2 * hi + 0] = e2.x;
                acc[mf][nt][2 * hi + 1] = e2.y;
                psum[nt * 2 + 0] += e2.x;
                psum[nt * 2 + 1] += e2.y;
            }
        }

    #pragma unroll
    for (int j = 0; j < 16; ++j) {
        psum[j] += __shfl_xor_sync(0xffffffffu, psum[j], 4);
        psum[j] += __shfl_xor_sync(0xffffffffu, psum[j], 8);
        psum[j] += __shfl_xor_sync(0xffffffffu, psum[j], 16);
        psum[j] = 1.0f / psum[j];            // inv(colsum)
    }

    // ---- phase 2: out[row] = sum_col e * inv * h (h from resident fp16 slots) ----
    const uint32_t aslot = smem_u32 + AOFF(wn);
    float part[8];
    #pragma unroll
    for (int mf = 0; mf < 4; ++mf)
        #pragma unroll
        for (int hi = 0; hi < 2; ++hi) {
            int row = wm * 64 + mf * 16 + hi * 8 + g;
            float p = 0.0f;
            #pragma unroll
            for (int nt = 0; nt < 8; ++nt) {
                uint32_t b_ = (uint32_t)(row * 128 + (nt * 8 + 2 * tig) * 2);
                uint32_t sw_ = b_ ^ ((b_ >> 3) & 0x70);
                uint32_t u_;
                asm volatile("ld.shared.b32 %0, [%1];" : "=r"(u_) : "r"(aslot + sw_));
                float2 hh = __half22float2(*(__half2*)&u_);
                p += acc[mf][nt][2 * hi + 0] * psum[nt * 2 + 0] * hh.x;
                p += acc[mf][nt][2 * hi + 1] * psum[nt * 2 + 1] * hh.y;
            }
            part[mf * 2 + hi] = p;
        }

    #pragma unroll
    for (int s = 0; s < 8; ++s) {
        part[s] += __shfl_xor_sync(0xffffffffu, part[s], 1);
        part[s] += __shfl_xor_sync(0xffffffffu, part[s], 2);
    }
    float* rowpart = (float*)(dynsmem + RP_OFF);
    if (tig == 0) {
        #pragma unroll
        for (int s = 0; s < 8; ++s) {
            int row = wm * 64 + (s >> 1) * 16 + (s & 1) * 8 + g;
            rowpart[wn * 128 + row] = part[s];
        }
    }
    __syncthreads();

    if (tid < 128) {
        float v = rowpart[tid] + rowpart[128 + tid] + rowpart[256 + tid] + rowpart[384 + tid];
        out[(size_t)blockIdx.x * 128 + tid] = v;
    }
}

extern "C" void kernel_launch(void* const* d_in, const int* in_sizes, int n_in,
                              void* d_out, int out_size) {
    const float* h    = (const float*)d_in[0];  // [4096, 64, 256]
    const float* W    = (const float*)d_in[1];  // [256, 256]
    const float* bias = (const float*)d_in[2];  // [64, 256]
    float* out = (float*)d_out;                 // [4096, 64]

    pack_w_kernel<<<8, 256>>>(W);
    pack_bias_kernel<<<32, 256>>>(bias);

    cudaFuncSetAttribute(aspect_attention_kernel,
                         cudaFuncAttributeMaxDynamicSharedMemorySize, SMEM_BYTES);
    aspect_attention_kernel<<<2048, THREADS, SMEM_BYTES>>>(h, out);
}

// round 17
// speedup vs baseline: 1.3843x; 1.1266x over previous
#include <cuda_runtime.h>
#include <cuda_fp16.h>
#include <cstdint>
#include <cstddef>

// AspectAttention round 10: 2 CTAs/SM. CTA = 1 batch (64 rows) x 256 cols,
// 4096 CTAs x 256 thr (8 warps, 2m x 4n, warp tile 32x64), fp16 mma m16n8k16.
// W streamed as 16KB k16-pair stages (cp.async, 3-stage ring) from the packed
// global layout (L2-resident). A staged fp16 in 4 fixed 8KB slots (ldmatrix.x4,
// XOR swizzle). exp via ex2.approx.f16x2. Phase-2 h from resident fp16 slots.
// Bias read from packed global (coalesced LDG).

#define THREADS   256
#define BS(s)     ((s) * 16384)               // 3 B stages: 16KB each
#define AOFF(c)   (49152 + (c) * 8192)        // 4 fixed A slots: 64 rows x 128B
#define CP_OFF    81920                        // colpart: 512 floats
#define RP_OFF    83968                        // rowpart: 256 floats
#define SMEM_BYTES 84992                       // 83 KB -> 2 CTAs/SM

__device__ __half    g_Wpack[8 * 256 * 4 * 8]; // [pair][col][tig][8 halves = uint4]
__device__ uint32_t  g_biaspack[4 * 64 * 32];  // [wn][j=rb*8+nt][lane] half2

// ---------------- helpers ----------------
__device__ __forceinline__ float tanh_fast(float x) {
    float y; asm("tanh.approx.f32 %0, %1;" : "=f"(y) : "f"(x)); return y;
}
__device__ __forceinline__ uint32_t pack2(float hi, float lo) {
    uint32_t r; asm("cvt.rn.f16x2.f32 %0, %1, %2;" : "=r"(r) : "f"(hi), "f"(lo)); return r;
}
__device__ __forceinline__ void mma_fp16(float (&c)[4],
                                         uint32_t a0, uint32_t a1, uint32_t a2, uint32_t a3,
                                         uint32_t b0, uint32_t b1) {
    asm volatile(
        "mma.sync.aligned.m16n8k16.row.col.f32.f16.f16.f32 "
        "{%0,%1,%2,%3},{%4,%5,%6,%7},{%8,%9},{%0,%1,%2,%3};"
        : "+f"(c[0]), "+f"(c[1]), "+f"(c[2]), "+f"(c[3])
        : "r"(a0), "r"(a1), "r"(a2), "r"(a3), "r"(b0), "r"(b1));
}
__device__ __forceinline__ void ldmatrix4(uint32_t (&d)[4], uint32_t addr) {
    asm volatile("ldmatrix.sync.aligned.m8n8.x4.shared.b16 {%0,%1,%2,%3}, [%4];"
                 : "=r"(d[0]), "=r"(d[1]), "=r"(d[2]), "=r"(d[3]) : "r"(addr));
}
__device__ __forceinline__ void cp_async16(uint32_t sa, const void* g) {
    asm volatile("cp.async.cg.shared.global [%0], [%1], 16;" :: "r"(sa), "l"(g));
}

// ---------------- W pack: uint4 = B frags for k16-step pair (2p, 2p+1) ----------
__global__ void pack_w_kernel(const float* __restrict__ W) {
    const int p   = blockIdx.x;      // pair 0..7
    const int col = threadIdx.x;     // 0..255
    #pragma unroll
    for (int t = 0; t < 4; ++t) {
        __half* dst = g_Wpack + (((p * 256 + col) * 4 + t) * 8);
        const int k0 = 32 * p + 2 * t;
        dst[0] = __float2half_rn(W[(k0)     * 256 + col]);
        dst[1] = __float2half_rn(W[(k0 + 1) * 256 + col]);
        dst[2] = __float2half_rn(W[(k0 + 8) * 256 + col]);
        dst[3] = __float2half_rn(W[(k0 + 9) * 256 + col]);
        const int k1 = k0 + 16;
        dst[4] = __float2half_rn(W[(k1)     * 256 + col]);
        dst[5] = __float2half_rn(W[(k1 + 1) * 256 + col]);
        dst[6] = __float2half_rn(W[(k1 + 8) * 256 + col]);
        dst[7] = __float2half_rn(W[(k1 + 9) * 256 + col]);
    }
}

// ---------------- bias pack: [wn][j=rb*8+nt][lane], n = rb*8+g, col = wn*64+nt*8+2tig
__global__ void pack_bias_kernel(const float* __restrict__ bias) {
    int idx  = blockIdx.x * 256 + threadIdx.x;   // 0..8191
    int wn   = idx >> 11;
    int j    = (idx >> 5) & 63;
    int lane = idx & 31;
    int rb = j >> 3, nt = j & 7;
    int g = lane >> 2, tig = lane & 3;
    int n   = rb * 8 + g;
    int col = wn * 64 + nt * 8 + 2 * tig;
    __half2 v = __floats2half2_rn(bias[n * 256 + col], bias[n * 256 + col + 1]);
    g_biaspack[idx] = *(uint32_t*)&v;
}

// ---------------- main kernel ----------------
__global__ __launch_bounds__(THREADS, 2)
void aspect_attention_kernel(const float* __restrict__ h,
                             float* __restrict__ out) {
    extern __shared__ __align__(16) char dynsmem[];
    const uint32_t smem_u32 = (uint32_t)__cvta_generic_to_shared(dynsmem);

    const int tid  = threadIdx.x;
    const int w    = tid >> 5;
    const int lane = tid & 31;
    const int g    = lane >> 2;
    const int tig  = lane & 3;
    const int wm   = w & 1;        // row block: wm*32
    const int wn   = w >> 1;       // col block: wn*64

    const int arow0  = wm * 32 + (lane & 7) + ((lane >> 3) & 1) * 8;  // + mf*16
    const uint32_t X  = ((uint32_t)(lane & 7)) << 4;
    const uint32_t kL = ((uint32_t)((lane >> 4) & 1)) * 16;

    const int srow  = tid >> 4;      // + j*16 (rows 0..63)
    const int squad = tid & 15;

    const float* hb = h + (size_t)blockIdx.x * (64 * 256);

    float acc[2][8][4];
    #pragma unroll
    for (int mf = 0; mf < 2; ++mf)
        #pragma unroll
        for (int nt = 0; nt < 8; ++nt)
            #pragma unroll
            for (int i = 0; i < 4; ++i) acc[mf][nt][i] = 0.0f;

    float4 buf[4];

    #define ISSUE_B(p) do {                                                       \
        const char* bsrc_ = (const char*)g_Wpack + (p) * 16384;                   \
        uint32_t dst_ = smem_u32 + BS((p) % 3);                                   \
        _Pragma("unroll")                                                         \
        for (int it = 0; it < 4; ++it) {                                          \
            int i_ = it * THREADS + tid;                                          \
            cp_async16(dst_ + i_ * 16, bsrc_ + i_ * 16);                          \
        }                                                                         \
        asm volatile("cp.async.commit_group;");                                   \
    } while (0)

    #define LDG_CHUNK(c) do {                                                     \
        const float* src_ = hb + (c) * 64;                                        \
        _Pragma("unroll")                                                         \
        for (int j = 0; j < 4; ++j)                                               \
            buf[j] = *(const float4*)(src_ + (srow + j * 16) * 256 + squad * 4);  \
    } while (0)

    #define STS_CHUNK(c) do {                                                     \
        uint32_t base_ = smem_u32 + AOFF(c);                                      \
        _Pragma("unroll")                                                         \
        for (int j = 0; j < 4; ++j) {                                             \
            uint32_t b_ = (uint32_t)((srow + j * 16) * 128 + squad * 8);          \
            uint32_t sw_ = b_ ^ ((b_ >> 3) & 0x70);                               \
            uint32_t u0_ = pack2(buf[j].y, buf[j].x);                             \
            uint32_t u1_ = pack2(buf[j].w, buf[j].z);                             \
            asm volatile("st.shared.v2.u32 [%0], {%1,%2};"                        \
                         :: "r"(base_ + sw_), "r"(u0_), "r"(u1_));                \
        }                                                                         \
    } while (0)

    uint32_t A0[2][4], A1[2][4];
    uint32_t Bb[2][4];

    #define LOAD_A(slot, ss, A_) do {                                             \
        uint32_t ab_ = smem_u32 + AOFF(slot);                                     \
        _Pragma("unroll")                                                         \
        for (int mf = 0; mf < 2; ++mf) {                                          \
            uint32_t b_ = (uint32_t)((arow0 + mf * 16) * 128) + kL + (ss) * 32;   \
            ldmatrix4(A_[mf], ab_ + (b_ ^ X));                                    \
        }                                                                         \
    } while (0)

    #define LDB4(p, nt, slot) do {                                                \
        uint32_t ba_ = smem_u32 + BS((p) % 3) +                                   \
            (uint32_t)((((wn * 64 + (nt) * 8 + g) * 4) + tig) * 16);              \
        asm volatile("ld.shared.v4.u32 {%0,%1,%2,%3}, [%4];"                      \
                     : "=r"(Bb[slot][0]), "=r"(Bb[slot][1]),                      \
                       "=r"(Bb[slot][2]), "=r"(Bb[slot][3]) : "r"(ba_));          \
    } while (0)

    // pair q: k16-steps 2q (A0) and 2q+1 (A1); Bb[0] preloaded with (q, nt=0)
    #define PAIR_BODY(q) do {                                                     \
        _Pragma("unroll")                                                         \
        for (int nt = 0; nt < 8; ++nt) {                                          \
            if (nt < 7) LDB4((q), nt + 1, (nt + 1) & 1);                          \
            _Pragma("unroll")                                                     \
            for (int mf = 0; mf < 2; ++mf)                                        \
                mma_fp16(acc[mf][nt], A0[mf][0], A0[mf][1], A0[mf][2], A0[mf][3], \
                         Bb[nt & 1][0], Bb[nt & 1][1]);                           \
            _Pragma("unroll")                                                     \
            for (int mf = 0; mf < 2; ++mf)                                        \
                mma_fp16(acc[mf][nt], A1[mf][0], A1[mf][1], A1[mf][2], A1[mf][3], \
                         Bb[nt & 1][2], Bb[nt & 1][3]);                           \
        }                                                                         \
    } while (0)

    // PAIRSTEP: wait for B(q), barrier, optionally issue B(qi), load A, compute.
    #define PAIRSTEP(q, nwait, qi) do {                                           \
        asm volatile("cp.async.wait_group %0;" :: "n"(nwait));                    \
        __syncthreads();                                                          \
        LDB4((q), 0, 0);                                                          \
        if ((qi) <= 7) ISSUE_B(qi);                                               \
        LOAD_A((q) >> 1, ((q) & 1) * 2 + 0, A0);                                  \
        LOAD_A((q) >> 1, ((q) & 1) * 2 + 1, A1);                                  \
        PAIR_BODY(q);                                                             \
    } while (0)

    // ---- prologue ----
    ISSUE_B(0); ISSUE_B(1); ISSUE_B(2);
    LDG_CHUNK(0);
    STS_CHUNK(0);
    LDG_CHUNK(1);

    // ---- main loop: 8 pairs, A chunk staging between chunks ----
    PAIRSTEP(0, 2, 99);
    PAIRSTEP(1, 1, 3);
    STS_CHUNK(1); LDG_CHUNK(2);
    PAIRSTEP(2, 1, 4);
    PAIRSTEP(3, 1, 5);
    STS_CHUNK(2); LDG_CHUNK(3);
    PAIRSTEP(4, 1, 6);
    PAIRSTEP(5, 1, 7);
    STS_CHUNK(3);
    PAIRSTEP(6, 1, 99);
    PAIRSTEP(7, 0, 99);

    // ---- epilogue phase 1: e = exp(tanh(s + bias)); 32-row column partials ----
    const float LOG2E = 1.4426950408889634f;
    float psum[16];
    #pragma unroll
    for (int j = 0; j < 16; ++j) psum[j] = 0.0f;

    #pragma unroll
    for (int mf = 0; mf < 2; ++mf)
        #pragma unroll
        for (int hi = 0; hi < 2; ++hi) {
            const int rb = wm * 4 + mf * 2 + hi;
            #pragma unroll
            for (int nt = 0; nt < 8; ++nt) {
                uint32_t bu = g_biaspack[(wn * 64 + rb * 8 + nt) * 32 + lane];
                float2 bb = __half22float2(*(__half2*)&bu);
                float t0 = tanh_fast(acc[mf][nt][2 * hi + 0] + bb.x) * LOG2E;
                float t1 = tanh_fast(acc[mf][nt][2 * hi + 1] + bb.y) * LOG2E;
                uint32_t up = pack2(t1, t0);
                uint32_t ep;
                asm("ex2.approx.f16x2 %0, %1;" : "=r"(ep) : "r"(up));
                float2 e2 = __half22float2(*(__half2*)&ep);
                acc[mf][nt][2 * hi + 0] = e2.x;
                acc[mf][nt][2 * hi + 1] = e2.y;
                psum[nt * 2 + 0] += e2.x;
                psum[nt * 2 + 1] += e2.y;
            }
        }

    // butterfly over g: full 32-row partial in every lane
    #pragma unroll
    for (int j = 0; j < 16; ++j) {
        psum[j] += __shfl_xor_sync(0xffffffffu, psum[j], 4);
        psum[j] += __shfl_xor_sync(0xffffffffu, psum[j], 8);
        psum[j] += __shfl_xor_sync(0xffffffffu, psum[j], 16);
    }

    // combine with wm-partner warp (w^1) -> inv of full 64-row colsum
    float* colpart = (float*)(dynsmem + CP_OFF);
    __syncthreads();
    if (g == 0) {
        #pragma unroll
        for (int nt = 0; nt < 8; ++nt) {
            colpart[w * 64 + nt * 8 + 2 * tig + 0] = psum[nt * 2 + 0];
            colpart[w * 64 + nt * 8 + 2 * tig + 1] = psum[nt * 2 + 1];
        }
    }
    __syncthreads();
    {
        const float* pc = colpart + (w ^ 1) * 64;
        #pragma unroll
        for (int nt = 0; nt < 8; ++nt) {
            psum[nt * 2 + 0] = 1.0f / (psum[nt * 2 + 0] + pc[nt * 8 + 2 * tig + 0]);
            psum[nt * 2 + 1] = 1.0f / (psum[nt * 2 + 1] + pc[nt * 8 + 2 * tig + 1]);
        }
    }

    // ---- phase 2: out[row] = sum_col e * inv * h (h from fp16 slot wn) ----
    const uint32_t aslot = smem_u32 + AOFF(wn);
    float part[4];
    #pragma unroll
    for (int mf = 0; mf < 2; ++mf)
        #pragma unroll
        for (int hi = 0; hi < 2; ++hi) {
            int row = wm * 32 + mf * 16 + hi * 8 + g;
            float p = 0.0f;
            #pragma unroll
            for (int nt = 0; nt < 8; ++nt) {
                uint32_t b_ = (uint32_t)(row * 128 + (nt * 8 + 2 * tig) * 2);
                uint32_t sw_ = b_ ^ ((b_ >> 3) & 0x70);
                uint32_t u_;
                asm volatile("ld.shared.b32 %0, [%1];" : "=r"(u_) : "r"(aslot + sw_));
                float2 hh = __half22float2(*(__half2*)&u_);
                p += acc[mf][nt][2 * hi + 0] * psum[nt * 2 + 0] * hh.x;
                p += acc[mf][nt][2 * hi + 1] * psum[nt * 2 + 1] * hh.y;
            }
            part[mf * 2 + hi] = p;
        }

    #pragma unroll
    for (int s = 0; s < 4; ++s) {
        part[s] += __shfl_xor_sync(0xffffffffu, part[s], 1);
        part[s] += __shfl_xor_sync(0xffffffffu, part[s], 2);
    }
    float* rowpart = (float*)(dynsmem + RP_OFF);
    if (tig == 0) {
        #pragma unroll
        for (int s = 0; s < 4; ++s) {
            int row = wm * 32 + (s >> 1) * 16 + (s & 1) * 8 + g;
            rowpart[wn * 64 + row] = part[s];
        }
    }
    __syncthreads();

    if (tid < 64) {
        float v = rowpart[tid] + rowpart[64 + tid] + rowpart[128 + tid] + rowpart[192 + tid];
        out[(size_t)blockIdx.x * 64 + tid] = v;
    }
}

extern "C" void kernel_launch(void* const* d_in, const int* in_sizes, int n_in,
                              void* d_out, int out_size) {
    const float* h    = (const float*)d_in[0];  // [4096, 64, 256]
    const float* W    = (const float*)d_in[1];  // [256, 256]
    const float* bias = (const float*)d_in[2];  // [64, 256]
    float* out = (float*)d_out;                 // [4096, 64]

    pack_w_kernel<<<8, 256>>>(W);
    pack_bias_kernel<<<32, 256>>>(bias);

    cudaFuncSetAttribute(aspect_attention_kernel,
                         cudaFuncAttributeMaxDynamicSharedMemorySize, SMEM_BYTES);
    aspect_attention_kernel<<<4096, THREADS, SMEM_BYTES>>>(h, out);
}